// round 11
// baseline (speedup 1.0000x reference)
#include <cuda_runtime.h>
#include <math.h>

#define THREADS 256
#define BLOCKS_PER_SM 6
#define MAXB 64

__global__ void zero_out_kernel(float* out, int n) {
    int i = blockIdx.x * blockDim.x + threadIdx.x;
    if (i < n) out[i] = 0.0f;
}

__global__ __launch_bounds__(THREADS, BLOCKS_PER_SM)
void trajectory_score_kernel(
    const float4* __restrict__ up, const float4* __restrict__ uo,
    const float* __restrict__ hArr, const float* __restrict__ lamArr,
    const float* __restrict__ thArr, float* __restrict__ out,
    int B, int totalGroups, int groupsPerSeg)
{
    __shared__ float s_c[MAXB], s_q[MAXB], s_nk2[MAXB], s_th[MAXB];
    __shared__ float s_log[MAXB], s_hit[MAXB];

    int tid = threadIdx.x;
    if (tid < B) {
        float h   = hArr[tid];
        float lam = lamArr[tid];
        float th  = thArr[tid];
        s_c[tid]   = h * lam / (1.0f - expf(-lam));   // full precision, once per block
        s_q[tid]   = 1.0f - h;
        s_nk2[tid] = -(lam / th) * 1.44269504088896340736f;
        s_th[tid]  = th;
        s_log[tid] = 0.0f;
        s_hit[tid] = 0.0f;
    }
    __syncthreads();

    // Contiguous chunk per block: balanced to within one iteration across the
    // whole (single-wave) grid. chunk < groupsPerSeg, so each thread crosses
    // at most one segment boundary.
    int chunk = (totalGroups + gridDim.x - 1) / gridDim.x;
    int start = blockIdx.x * chunk;
    int end   = min(start + chunk, totalGroups);

    float acc_log = 0.0f, acc_hit = 0.0f;
    int g0 = start + tid;
    if (g0 < end) {
        int curSeg = g0 / groupsPerSeg;
        int segEnd = (curSeg + 1) * groupsPerSeg;
        float c   = s_c[curSeg];
        float q   = s_q[curSeg];
        float nk2 = s_nk2[curSeg];
        float th  = s_th[curSeg];

        for (int g = g0; g < end; g += THREADS) {
            if (g >= segEnd) {   // rare: at most once per thread
                if (acc_log != 0.0f) atomicAdd(&s_log[curSeg], acc_log);
                if (acc_hit != 0.0f) atomicAdd(&s_hit[curSeg], acc_hit);
                acc_log = 0.0f; acc_hit = 0.0f;
                curSeg = g / groupsPerSeg;
                segEnd = (curSeg + 1) * groupsPerSeg;
                c = s_c[curSeg]; q = s_q[curSeg]; nk2 = s_nk2[curSeg]; th = s_th[curSeg];
            }

            float4 a0 = __ldg(&up[3 * g + 0]);
            float4 a1 = __ldg(&up[3 * g + 1]);
            float4 a2 = __ldg(&up[3 * g + 2]);
            float4 b0 = __ldg(&uo[3 * g + 0]);
            float4 b1 = __ldg(&uo[3 * g + 1]);
            float4 b2 = __ldg(&uo[3 * g + 2]);

            float d0  = a0.x - b0.x, d1  = a0.y - b0.y, d2  = a0.z - b0.z;
            float d3  = a0.w - b0.w, d4  = a1.x - b1.x, d5  = a1.y - b1.y;
            float d6  = a1.z - b1.z, d7  = a1.w - b1.w, d8  = a2.x - b2.x;
            float d9  = a2.y - b2.y, d10 = a2.z - b2.z, d11 = a2.w - b2.w;

            float s2[4];
            s2[0] = d0 * d0 + d1 * d1 + d2 * d2;
            s2[1] = d3 * d3 + d4 * d4 + d5 * d5;
            s2[2] = d6 * d6 + d7 * d7 + d8 * d8;
            s2[3] = d9 * d9 + d10 * d10 + d11 * d11;

            #pragma unroll
            for (int r = 0; r < 4; r++) {
                float s = s2[r];
                bool close = s < th;
                float ph = c * exp2f(s * nk2);   // FMUL + MUFU.EX2 + FMUL
                float p  = ph + q;
                float rp = __frcp_rn(p);         // MUFU.RCP
                float ratio = ph * rp;
                float lp = __logf(p);            // MUFU.LG2 + FMUL
                acc_log += close ? lp : 0.0f;
                acc_hit += (close && ratio > 0.95f) ? ratio : 0.0f;
            }
        }
        if (acc_log != 0.0f) atomicAdd(&s_log[curSeg], acc_log);
        if (acc_hit != 0.0f) atomicAdd(&s_hit[curSeg], acc_hit);
    }
    __syncthreads();

    if (tid < B) {
        float tl = s_log[tid], thh = s_hit[tid];
        if (tl  != 0.0f) atomicAdd(&out[tid], tl);
        if (thh != 0.0f) {
            atomicAdd(&out[B + tid],     thh);
            atomicAdd(&out[2 * B + tid], thh);
        }
    }
}

extern "C" void kernel_launch(void* const* d_in, const int* in_sizes, int n_in,
                              void* d_out, int out_size) {
    const float* up  = (const float*)d_in[0];  // u_pred [N,3]
    const float* uo  = (const float*)d_in[1];  // u_obs  [N,3]
    const float* h   = (const float*)d_in[2];  // [B]
    const float* lam = (const float*)d_in[3];  // [B]
    const float* th  = (const float*)d_in[4];  // [B]
    float* out = (float*)d_out;                // [3*B]

    int B    = in_sizes[2];
    int N    = in_sizes[0] / 3;                // total rows
    int nper = N / B;                          // 100000, divisible by 4
    int groupsPerSeg = nper / 4;               // 25000
    int totalGroups  = N / 4;                  // 1.6M

    // One wave exactly: 6 blocks/SM guaranteed by __launch_bounds__(256, 6).
    int sms = 148;
    cudaDeviceGetAttribute(&sms, cudaDevAttrMultiProcessorCount, 0);
    int grid = sms * BLOCKS_PER_SM;

    zero_out_kernel<<<1, 256>>>(out, out_size);
    trajectory_score_kernel<<<grid, THREADS>>>(
        (const float4*)up, (const float4*)uo, h, lam, th, out,
        B, totalGroups, groupsPerSeg);
}

// round 12
// speedup vs baseline: 1.4768x; 1.4768x over previous
#include <cuda_runtime.h>
#include <math.h>

#define THREADS 256
#define BLOCKS_PER_SM 6

__global__ void zero_out_kernel(float* out, int n) {
    int i = blockIdx.x * blockDim.x + threadIdx.x;
    if (i < n) out[i] = 0.0f;
}

__global__ __launch_bounds__(THREADS, BLOCKS_PER_SM)
void trajectory_score_kernel(
    const float4* __restrict__ up, const float4* __restrict__ uo,
    const float* __restrict__ hArr, const float* __restrict__ lamArr,
    const float* __restrict__ thArr, float* __restrict__ out,
    int B, int blocksPerSeg, int groupsPerSeg, int vec4PerSeg)
{
    int seg  = blockIdx.x / blocksPerSeg;
    int part = blockIdx.x - seg * blocksPerSeg;

    float h   = hArr[seg];
    float lam = lamArr[seg];
    float th  = thArr[seg];
    float c = h * lam / (1.0f - expf(-lam));   // full precision, once per block
    float q = 1.0f - h;
    float nk2 = -(lam / th) * 1.44269504088896340736f;  // e^{-lam*s/th} = 2^{s*nk2}

    const float4* upS = up + (size_t)seg * vec4PerSeg;
    const float4* uoS = uo + (size_t)seg * vec4PerSeg;

    float acc_log = 0.0f;
    float acc_hit = 0.0f;

    int stride = blocksPerSeg * THREADS;
    for (int g = part * THREADS + threadIdx.x; g < groupsPerSeg; g += stride) {
        float4 a0 = __ldg(&upS[3 * g + 0]);
        float4 a1 = __ldg(&upS[3 * g + 1]);
        float4 a2 = __ldg(&upS[3 * g + 2]);
        float4 b0 = __ldg(&uoS[3 * g + 0]);
        float4 b1 = __ldg(&uoS[3 * g + 1]);
        float4 b2 = __ldg(&uoS[3 * g + 2]);

        float d0  = a0.x - b0.x, d1  = a0.y - b0.y, d2  = a0.z - b0.z;
        float d3  = a0.w - b0.w, d4  = a1.x - b1.x, d5  = a1.y - b1.y;
        float d6  = a1.z - b1.z, d7  = a1.w - b1.w, d8  = a2.x - b2.x;
        float d9  = a2.y - b2.y, d10 = a2.z - b2.z, d11 = a2.w - b2.w;

        float s2[4];
        s2[0] = d0 * d0 + d1 * d1 + d2 * d2;
        s2[1] = d3 * d3 + d4 * d4 + d5 * d5;
        s2[2] = d6 * d6 + d7 * d7 + d8 * d8;
        s2[3] = d9 * d9 + d10 * d10 + d11 * d11;

        #pragma unroll
        for (int r = 0; r < 4; r++) {
            float s = s2[r];
            bool close = s < th;
            float ph = c * exp2f(s * nk2);   // FMUL + MUFU.EX2 + FMUL
            float p  = ph + q;
            float rp = __frcp_rn(p);         // MUFU.RCP
            float ratio = ph * rp;
            float lp = __logf(p);            // MUFU.LG2 + FMUL
            acc_log += close ? lp : 0.0f;
            acc_hit += (close && ratio > 0.95f) ? ratio : 0.0f;
        }
    }

    // warp reduce
    #pragma unroll
    for (int o = 16; o > 0; o >>= 1) {
        acc_log += __shfl_down_sync(0xffffffffu, acc_log, o);
        acc_hit += __shfl_down_sync(0xffffffffu, acc_hit, o);
    }

    __shared__ float s_log[THREADS / 32];
    __shared__ float s_hit[THREADS / 32];
    int lane = threadIdx.x & 31;
    int warp = threadIdx.x >> 5;
    if (lane == 0) { s_log[warp] = acc_log; s_hit[warp] = acc_hit; }
    __syncthreads();

    if (threadIdx.x == 0) {
        float tl = 0.0f, thit = 0.0f;
        #pragma unroll
        for (int w = 0; w < THREADS / 32; w++) { tl += s_log[w]; thit += s_hit[w]; }
        atomicAdd(&out[seg],         tl);
        atomicAdd(&out[B + seg],     thit);
        atomicAdd(&out[2 * B + seg], thit);
    }
}

extern "C" void kernel_launch(void* const* d_in, const int* in_sizes, int n_in,
                              void* d_out, int out_size) {
    const float* up  = (const float*)d_in[0];  // u_pred [N,3]
    const float* uo  = (const float*)d_in[1];  // u_obs  [N,3]
    const float* h   = (const float*)d_in[2];  // [B]
    const float* lam = (const float*)d_in[3];  // [B]
    const float* th  = (const float*)d_in[4];  // [B]
    float* out = (float*)d_out;                // [3*B]

    int B    = in_sizes[2];
    int N    = in_sizes[0] / 3;                // total rows
    int nper = N / B;                          // 100000, divisible by 4
    int groupsPerSeg = nper / 4;               // 25000
    int vec4PerSeg   = (nper * 3) / 4;         // 75000

    // One wave exactly: blocksPerSeg = floor(SMs * 6 / B)  (912/64 = 14 on GB300)
    int sms = 148;
    cudaDeviceGetAttribute(&sms, cudaDevAttrMultiProcessorCount, 0);
    int blocksPerSeg = (sms * BLOCKS_PER_SM) / B;
    if (blocksPerSeg < 1) blocksPerSeg = 1;

    zero_out_kernel<<<1, 256>>>(out, out_size);
    trajectory_score_kernel<<<B * blocksPerSeg, THREADS>>>(
        (const float4*)up, (const float4*)uo, h, lam, th, out,
        B, blocksPerSeg, groupsPerSeg, vec4PerSeg);
}

// round 15
// speedup vs baseline: 1.5691x; 1.0625x over previous
#include <cuda_runtime.h>
#include <math.h>

#define THREADS 256
#define WARPS (THREADS / 32)
#define BLOCKS_PER_SM 6

__global__ void zero_out_kernel(float* out, int n) {
    int i = blockIdx.x * blockDim.x + threadIdx.x;
    if (i < n) out[i] = 0.0f;
}

__global__ __launch_bounds__(THREADS, BLOCKS_PER_SM)
void trajectory_score_kernel(
    const float4* __restrict__ up, const float4* __restrict__ uo,
    const float* __restrict__ hArr, const float* __restrict__ lamArr,
    const float* __restrict__ thArr, float* __restrict__ out,
    int B, int blocksPerSeg, int groupsPerSeg, int vec4PerSeg)
{
    // Per-warp staging: [warp][tensor][96 float4] = 1536 B per tensor per warp.
    __shared__ float4 stage[WARPS][2][96];

    int seg  = blockIdx.x / blocksPerSeg;
    int part = blockIdx.x - seg * blocksPerSeg;

    float h   = hArr[seg];
    float lam = lamArr[seg];
    float th  = thArr[seg];
    float c = h * lam / (1.0f - expf(-lam));   // full precision, once per block
    float q = 1.0f - h;
    float nk2 = -(lam / th) * 1.44269504088896340736f;  // e^{-lam*s/th} = 2^{s*nk2}

    const float4* upS = up + (size_t)seg * vec4PerSeg;
    const float4* uoS = uo + (size_t)seg * vec4PerSeg;
    int nF4 = vec4PerSeg;   // 75000 float4 per segment

    int lane = threadIdx.x & 31;
    int warp = threadIdx.x >> 5;

    float acc_log = 0.0f;
    float acc_hit = 0.0f;

    const float4 zf4 = make_float4(0.f, 0.f, 0.f, 0.f);
    int strideG = blocksPerSeg * WARPS * 32;   // groups advanced per warp-iteration

    // g0 is warp-uniform: all lanes iterate together; tails handled by predication.
    for (int g0 = (part * WARPS + warp) * 32; g0 < groupsPerSeg; g0 += strideG) {
        int f0 = 3 * g0;   // float4 index of this warp's tile start
        int i0 = f0 + lane, i1 = f0 + 32 + lane, i2 = f0 + 64 + lane;

        // Fully coalesced: each LDG.128 covers 512 contiguous bytes per warp.
        float4 a0 = (i0 < nF4) ? __ldcs(&upS[i0]) : zf4;
        float4 a1 = (i1 < nF4) ? __ldcs(&upS[i1]) : zf4;
        float4 a2 = (i2 < nF4) ? __ldcs(&upS[i2]) : zf4;
        float4 b0 = (i0 < nF4) ? __ldcs(&uoS[i0]) : zf4;
        float4 b1 = (i1 < nF4) ? __ldcs(&uoS[i1]) : zf4;
        float4 b2 = (i2 < nF4) ? __ldcs(&uoS[i2]) : zf4;

        __syncwarp();   // WAR: prior iteration's LDS reads done before overwrite
        stage[warp][0][lane]      = a0;
        stage[warp][0][lane + 32] = a1;
        stage[warp][0][lane + 64] = a2;
        stage[warp][1][lane]      = b0;
        stage[warp][1][lane + 32] = b1;
        stage[warp][1][lane + 64] = b2;
        __syncwarp();   // make stores visible within the warp

        // Each lane reads its 4-row group: 48 B at stride 48 -> conflict-free LDS.128 x3
        float4 r0 = stage[warp][0][3 * lane + 0];
        float4 r1 = stage[warp][0][3 * lane + 1];
        float4 r2 = stage[warp][0][3 * lane + 2];
        float4 s0 = stage[warp][1][3 * lane + 0];
        float4 s1 = stage[warp][1][3 * lane + 1];
        float4 s2v = stage[warp][1][3 * lane + 2];

        bool valid = (g0 + lane) < groupsPerSeg;

        float d0  = r0.x - s0.x,  d1  = r0.y - s0.y,  d2  = r0.z - s0.z;
        float d3  = r0.w - s0.w,  d4  = r1.x - s1.x,  d5  = r1.y - s1.y;
        float d6  = r1.z - s1.z,  d7  = r1.w - s1.w,  d8  = r2.x - s2v.x;
        float d9  = r2.y - s2v.y, d10 = r2.z - s2v.z, d11 = r2.w - s2v.w;

        float sq[4];
        sq[0] = d0 * d0 + d1 * d1 + d2 * d2;
        sq[1] = d3 * d3 + d4 * d4 + d5 * d5;
        sq[2] = d6 * d6 + d7 * d7 + d8 * d8;
        sq[3] = d9 * d9 + d10 * d10 + d11 * d11;

        #pragma unroll
        for (int r = 0; r < 4; r++) {
            float s = sq[r];
            bool close = valid && (s < th);
            float ph = c * exp2f(s * nk2);   // FMUL + MUFU.EX2 + FMUL
            float p  = ph + q;
            float rp = __frcp_rn(p);         // MUFU.RCP
            float ratio = ph * rp;
            float lp = __logf(p);            // MUFU.LG2 + FMUL
            acc_log += close ? lp : 0.0f;
            acc_hit += (close && ratio > 0.95f) ? ratio : 0.0f;
        }
    }

    // warp reduce
    #pragma unroll
    for (int o = 16; o > 0; o >>= 1) {
        acc_log += __shfl_down_sync(0xffffffffu, acc_log, o);
        acc_hit += __shfl_down_sync(0xffffffffu, acc_hit, o);
    }

    __shared__ float s_log[WARPS];
    __shared__ float s_hit[WARPS];
    if (lane == 0) { s_log[warp] = acc_log; s_hit[warp] = acc_hit; }
    __syncthreads();

    if (threadIdx.x == 0) {
        float tl = 0.0f, thit = 0.0f;
        #pragma unroll
        for (int w = 0; w < WARPS; w++) { tl += s_log[w]; thit += s_hit[w]; }
        atomicAdd(&out[seg],         tl);
        atomicAdd(&out[B + seg],     thit);
        atomicAdd(&out[2 * B + seg], thit);
    }
}

extern "C" void kernel_launch(void* const* d_in, const int* in_sizes, int n_in,
                              void* d_out, int out_size) {
    const float* up  = (const float*)d_in[0];  // u_pred [N,3]
    const float* uo  = (const float*)d_in[1];  // u_obs  [N,3]
    const float* h   = (const float*)d_in[2];  // [B]
    const float* lam = (const float*)d_in[3];  // [B]
    const float* th  = (const float*)d_in[4];  // [B]
    float* out = (float*)d_out;                // [3*B]

    int B    = in_sizes[2];
    int N    = in_sizes[0] / 3;                // total rows
    int nper = N / B;                          // 100000, divisible by 4
    int groupsPerSeg = nper / 4;               // 25000
    int vec4PerSeg   = (nper * 3) / 4;         // 75000

    // One wave: blocksPerSeg = floor(SMs * 6 / B)  (912/64 = 14 on GB300)
    int sms = 148;
    cudaDeviceGetAttribute(&sms, cudaDevAttrMultiProcessorCount, 0);
    int blocksPerSeg = (sms * BLOCKS_PER_SM) / B;
    if (blocksPerSeg < 1) blocksPerSeg = 1;

    zero_out_kernel<<<1, 256>>>(out, out_size);
    trajectory_score_kernel<<<B * blocksPerSeg, THREADS>>>(
        (const float4*)up, (const float4*)uo, h, lam, th, out,
        B, blocksPerSeg, groupsPerSeg, vec4PerSeg);
}